// round 15
// baseline (speedup 1.0000x reference)
#include <cuda_runtime.h>
#include <cstdint>
#include <math.h>

#define BATCH 4
#define SEQ   4096
#define DIM   512
#define ROWS  (BATCH*SEQ)   // 16384
#define NCHUNK 64
#define CHUNK  (SEQ/NCHUNK) // 64
#define CLSZ   8            // cluster size for chain

// GEMM smem layout (dynamic): Xd dup-pairs [2][16][260], Ws [2][16][132]
#define XD_STRIDE 260
#define XD_PLANE  (16*XD_STRIDE)           // 4160 floats
#define WS_PLANE  (16*132)                 // 2112 floats
#define GEMM_SMEM_BYTES ((2*XD_PLANE + 2*WS_PLANE)*4)   // 50176 B

// ---- scratch (no cudaMalloc allowed) ----
__device__ float g_R[ROWS*DIM];
__device__ float g_G[ROWS*DIM];
__device__ float g_C[ROWS*DIM];
__device__ float g_S[ROWS*DIM];
__device__ float g_cf[BATCH*NCHUNK*DIM];
__device__ float g_cp[BATCH*NCHUNK*DIM];

// ---------------- helpers ----------------
__device__ __forceinline__ uint32_t smem_u32(const void* p) {
    return (uint32_t)__cvta_generic_to_shared(p);
}
__device__ __forceinline__ void fma2(unsigned long long& d, unsigned long long a, unsigned long long b) {
    asm("fma.rn.f32x2 %0, %1, %2, %0;" : "+l"(d) : "l"(a), "l"(b));
}
__device__ __forceinline__ void unpack2(unsigned long long v, float& lo, float& hi) {
    asm("mov.b64 {%0, %1}, %2;" : "=f"(lo), "=f"(hi) : "l"(v));
}
__device__ __forceinline__ void mbar_init(uint32_t addr, uint32_t cnt) {
    asm volatile("mbarrier.init.shared.b64 [%0], %1;" :: "r"(addr), "r"(cnt) : "memory");
}
__device__ __forceinline__ void mbar_expect_tx(uint32_t addr, uint32_t bytes) {
    asm volatile("mbarrier.arrive.expect_tx.shared.b64 _, [%0], %1;" :: "r"(addr), "r"(bytes) : "memory");
}
__device__ __forceinline__ void st_async_u32(uint32_t raddr, uint32_t val, uint32_t rmbar) {
    asm volatile("st.async.weak.shared::cluster.mbarrier::complete_tx::bytes.b32 [%0], %1, [%2];"
                 :: "r"(raddr), "r"(val), "r"(rmbar) : "memory");
}
__device__ __forceinline__ void mbar_wait(uint32_t addr, uint32_t parity) {
    uint32_t done;
    asm volatile("{\n\t.reg .pred P;\n\t"
        "mbarrier.try_wait.parity.acquire.cta.shared::cta.b64 P, [%1], %2, 0x989680;\n\t"
        "selp.b32 %0, 1, 0, P;\n\t}"
        : "=r"(done) : "r"(addr), "r"(parity) : "memory");
    while (!done) {
        asm volatile("{\n\t.reg .pred P;\n\t"
            "mbarrier.try_wait.parity.acquire.cta.shared::cta.b64 P, [%1], %2, 0x989680;\n\t"
            "selp.b32 %0, 1, 0, P;\n\t}"
            : "=r"(done) : "r"(addr), "r"(parity) : "memory");
    }
}
#define CLUSTER_SYNC() do { \
    asm volatile("barrier.cluster.arrive.aligned;" ::: "memory"); \
    asm volatile("barrier.cluster.wait.aligned;"   ::: "memory"); } while (0)

// ============================================================
// Chunked linear scan for r
// ============================================================
__global__ void scan_local(const float* __restrict__ k, const float* __restrict__ v,
                           const float* __restrict__ decay, int store)
{
    int g = blockIdx.x*blockDim.x + threadIdx.x;
    int d = g % DIM;
    int c = (g / DIM) % NCHUNK;
    int b = g / (DIM*NCHUNK);
    float dec = decay[d >> 6];
    float r = store ? g_cp[g] : 0.0f;
    size_t base = ((size_t)b*SEQ + (size_t)c*CHUNK)*DIM + d;
    #pragma unroll 4
    for (int u = 0; u < CHUNK; u++) {
        size_t off = base + (size_t)u*DIM;
        r = fmaf(dec, r, k[off]*v[off]);
        if (store) g_R[off] = r;
    }
    if (!store) g_cf[g] = r;
}

__global__ void scan_prefix(const float* __restrict__ decay)
{
    int g = blockIdx.x*blockDim.x + threadIdx.x;
    int d = g % DIM;
    int b = g / DIM;
    float dec = decay[d >> 6];
    float dp = powf(dec, (float)CHUNK);
    float p = 0.0f;
    for (int c = 0; c < NCHUNK; c++) {
        int idx = (b*NCHUNK + c)*DIM + d;
        g_cp[idx] = p;
        p = g_cf[idx] + dp*p;
    }
}

// ============================================================
// fp32 GEMM: Y = act(X @ W^T + bias). Double-buffered, f32x2,
// X stored DUP-PAIRED in smem: one LDS128 -> two ready (a,a)
// operands; the 16 dup-MOVs per kk are gone.
// ============================================================
__global__ __launch_bounds__(256)
void gemm_kernel(const float* __restrict__ X, const float* __restrict__ W,
                 const float* __restrict__ bias, float* __restrict__ Y, int act)
{
    extern __shared__ __align__(16) float sm[];
    float* Xd = sm;                          // [2][16][XD_STRIDE]
    float* Ws = sm + 2*XD_PLANE;             // [2][16][132]

    const int K = DIM;
    int tid  = threadIdx.x;
    int m0   = blockIdx.y * 128;
    int n0   = blockIdx.x * 128;
    int rowc = (tid >> 4) << 3;
    int colc = (tid & 15) << 3;

    int lrow0 = tid >> 2,        lfc0 = (tid & 3) << 2;
    int lrow1 = (tid+256) >> 2,  lfc1 = ((tid+256) & 3) << 2;

    unsigned long long acc2[8][4];
    #pragma unroll
    for (int i = 0; i < 8; i++)
        #pragma unroll
        for (int j = 0; j < 4; j++) acc2[i][j] = 0ull;

    // loader: write X float4 as 4 dup float2s, W as before
    auto load_tile = [&](int buf, int kt) {
        float* xb = Xd + buf*XD_PLANE;
        float* wb = Ws + buf*WS_PLANE;
        float4 xv = *(const float4*)(X + (size_t)(m0+lrow0)*K + kt + lfc0);
        *(float2*)&xb[(lfc0+0)*XD_STRIDE + 2*lrow0] = make_float2(xv.x, xv.x);
        *(float2*)&xb[(lfc0+1)*XD_STRIDE + 2*lrow0] = make_float2(xv.y, xv.y);
        *(float2*)&xb[(lfc0+2)*XD_STRIDE + 2*lrow0] = make_float2(xv.z, xv.z);
        *(float2*)&xb[(lfc0+3)*XD_STRIDE + 2*lrow0] = make_float2(xv.w, xv.w);
        float4 wv = *(const float4*)(W + (size_t)(n0+lrow0)*K + kt + lfc0);
        wb[(lfc0+0)*132 + lrow0] = wv.x; wb[(lfc0+1)*132 + lrow0] = wv.y;
        wb[(lfc0+2)*132 + lrow0] = wv.z; wb[(lfc0+3)*132 + lrow0] = wv.w;
        float4 xv1 = *(const float4*)(X + (size_t)(m0+lrow1)*K + kt + lfc1);
        *(float2*)&xb[(lfc1+0)*XD_STRIDE + 2*lrow1] = make_float2(xv1.x, xv1.x);
        *(float2*)&xb[(lfc1+1)*XD_STRIDE + 2*lrow1] = make_float2(xv1.y, xv1.y);
        *(float2*)&xb[(lfc1+2)*XD_STRIDE + 2*lrow1] = make_float2(xv1.z, xv1.z);
        *(float2*)&xb[(lfc1+3)*XD_STRIDE + 2*lrow1] = make_float2(xv1.w, xv1.w);
        float4 wv1 = *(const float4*)(W + (size_t)(n0+lrow1)*K + kt + lfc1);
        wb[(lfc1+0)*132 + lrow1] = wv1.x; wb[(lfc1+1)*132 + lrow1] = wv1.y;
        wb[(lfc1+2)*132 + lrow1] = wv1.z; wb[(lfc1+3)*132 + lrow1] = wv1.w;
    };

    load_tile(0, 0);
    __syncthreads();

    for (int it = 0; it < K/16; it++) {
        int cur = it & 1;
        if (it + 1 < K/16) load_tile(1 - cur, (it+1)*16);

        const float* xbase = Xd + cur*XD_PLANE;
        const float* wbase = Ws + cur*WS_PLANE;
        #pragma unroll
        for (int kk = 0; kk < 16; kk++) {
            const float* xp = xbase + kk*XD_STRIDE + 2*rowc;
            ulonglong2 xa = *(const ulonglong2*)(xp     );   // (r0r0)(r1r1)
            ulonglong2 xbp= *(const ulonglong2*)(xp +  4);   // (r2r2)(r3r3)
            ulonglong2 xc = *(const ulonglong2*)(xp +  8);
            ulonglong2 xd = *(const ulonglong2*)(xp + 12);
            const float* wp = wbase + kk*132 + colc;
            ulonglong2 blo = *(const ulonglong2*)(wp);
            ulonglong2 bhi = *(const ulonglong2*)(wp + 4);
            unsigned long long ad[8] = {xa.x, xa.y, xbp.x, xbp.y, xc.x, xc.y, xd.x, xd.y};
            #pragma unroll
            for (int i = 0; i < 8; i++) {
                fma2(acc2[i][0], ad[i], blo.x);
                fma2(acc2[i][1], ad[i], blo.y);
                fma2(acc2[i][2], ad[i], bhi.x);
                fma2(acc2[i][3], ad[i], bhi.y);
            }
        }
        __syncthreads();
    }

    #pragma unroll
    for (int i = 0; i < 8; i++) {
        float out[8];
        #pragma unroll
        for (int jp = 0; jp < 4; jp++) unpack2(acc2[i][jp], out[2*jp], out[2*jp+1]);
        #pragma unroll
        for (int j = 0; j < 8; j++) {
            float val = out[j] + (bias ? bias[n0+colc+j] : 0.0f);
            if (act == 1) val = 1.0f/(1.0f + expf(-val));
            Y[(size_t)(m0+rowc+i)*DIM + n0+colc+j] = val;
        }
    }
}

// ============================================================
// Sequential chain: the proven structure (R6/R13), unchanged.
// ============================================================
__global__ void __launch_bounds__(256, 1) __cluster_dims__(CLSZ, 1, 1)
chain_kernel(const float* __restrict__ q, const float* __restrict__ A,
             const float* __restrict__ G, const float* __restrict__ C,
             float* __restrict__ Sout)
{
    __shared__ __align__(16) float bl[2][DIM];
    __shared__ __align__(16) float part[4][64];
    __shared__ __align__(8)  unsigned long long mbar[4];  // [buf][half]

    int rank = blockIdx.x & (CLSZ-1);
    int b    = blockIdx.x / CLSZ;
    int tid  = threadIdx.x;
    int w    = tid >> 5;
    int lane = tid & 31;
    int qw   = w >> 1;
    int rh   = w & 1;
    int jl   = rh*32 + lane;
    int jg   = rank*64 + jl;
    int kbase= qw*128;
    int hw   = qw >> 1;
    int myh  = rank >> 2;

    uint32_t bl_a = smem_u32(&bl[0][0]);
    uint32_t mb_a = smem_u32(&mbar[0]);
    uint32_t dmb  = mb_a - bl_a;

    if (tid == 0) {
        mbar_init(mb_a,      1);
        mbar_init(mb_a + 8,  1);
        mbar_init(mb_a + 16, 1);
        mbar_init(mb_a + 24, 1);
    }

    uint32_t rb[CLSZ];
    #pragma unroll
    for (int r = 0; r < CLSZ; r++)
        asm("mapa.shared::cluster.u32 %0, %1, %2;" : "=r"(rb[r]) : "r"(bl_a), "r"(r));

    unsigned long long a2[64];
    #pragma unroll
    for (int u = 0; u < 32; u++) {
        ulonglong2 av = *(const ulonglong2*)(A + (size_t)jg*DIM + kbase + 4*u);
        a2[2*u] = av.x; a2[2*u+1] = av.y;
    }

    const float* qb = q    + (size_t)b*SEQ*DIM;
    const float* Gb = G    + (size_t)b*SEQ*DIM;
    const float* Cb = C    + (size_t)b*SEQ*DIM;
    float*       Sb = Sout + (size_t)b*SEQ*DIM;

    CLUSTER_SYNC();

    int je = rank*64 + tid;
    float cc = 0.f, cg = 0.f, cq = 0.f;
    if (tid == 0) {
        mbar_expect_tx(mb_a,     1024);
        mbar_expect_tx(mb_a + 8, 1024);
    }
    if (tid < 64) {
        float g0 = Gb[je], q0 = qb[je];
        uint32_t bits = __float_as_uint((1.0f - g0) * q0);
        uint32_t moff = dmb + (uint32_t)myh*8u;
        #pragma unroll
        for (int r = 0; r < CLSZ; r++)
            st_async_u32(rb[r] + (uint32_t)je*4u, bits, rb[r] + moff);
        cc = Cb[je]; cg = Gb[DIM + je]; cq = qb[DIM + je];
    }

    for (int t = 0; t < SEQ; t++) {
        int p = t & 1;
        uint32_t ph = (t >> 1) & 1;

        float nc = 0.f, ng = 0.f, nq = 0.f;
        if (tid < 64) {
            if (t+1 < SEQ) nc = Cb[(size_t)(t+1)*DIM + je];
            if (t+2 < SEQ) { ng = Gb[(size_t)(t+2)*DIM + je]; nq = qb[(size_t)(t+2)*DIM + je]; }
        }
        if (tid == 0 && t+1 < SEQ) {
            mbar_expect_tx(mb_a + (uint32_t)(1-p)*16u,      1024);
            mbar_expect_tx(mb_a + (uint32_t)(1-p)*16u + 8u, 1024);
        }

        mbar_wait(mb_a + (uint32_t)p*16u + (uint32_t)hw*8u, ph);

        unsigned long long acc0 = 0ull, acc1 = 0ull;
        const float* blp = bl[p] + kbase;
        #pragma unroll
        for (int u = 0; u < 32; u++) {
            ulonglong2 bv = *(const ulonglong2*)(blp + 4*u);
            fma2(acc0, a2[2*u],   bv.x);
            fma2(acc1, a2[2*u+1], bv.y);
        }
        float x0, x1, y0, y1;
        unpack2(acc0, x0, x1);
        unpack2(acc1, y0, y1);
        part[qw][jl] = (x0 + x1) + (y0 + y1);

        __syncthreads();

        if (tid < 64) {
            float acc = (part[0][tid] + part[1][tid]) + (part[2][tid] + part[3][tid]);
            float s = tanhf(acc + cc);
            Sb[(size_t)t*DIM + je] = s;
            if (t+1 < SEQ) {
                uint32_t bits = __float_as_uint(fmaf(cg, s - cq, cq));
                uint32_t boff = (uint32_t)(1-p)*2048u + (uint32_t)je*4u;
                uint32_t moff = dmb + (uint32_t)(1-p)*16u + (uint32_t)myh*8u;
                #pragma unroll
                for (int r = 0; r < CLSZ; r++)
                    st_async_u32(rb[r] + boff, bits, rb[r] + moff);
            }
            cc = nc; cg = ng; cq = nq;
        }
    }
}

// ============================================================
// launch — fork-join stream overlap inside graph capture
// ============================================================
extern "C" void kernel_launch(void* const* d_in, const int* in_sizes, int n_in,
                              void* d_out, int out_size)
{
    const float* q     = (const float*)d_in[0];
    const float* k     = (const float*)d_in[1];
    const float* v     = (const float*)d_in[2];
    const float* A     = (const float*)d_in[3];
    const float* Bm    = (const float*)d_in[4];
    const float* gw    = (const float*)d_in[5];
    const float* gb    = (const float*)d_in[6];
    const float* ow    = (const float*)d_in[7];
    const float* ob    = (const float*)d_in[8];
    const float* decay = (const float*)d_in[9];
    float* out = (float*)d_out;

    float *R, *G, *C, *S;
    cudaGetSymbolAddress((void**)&R, g_R);
    cudaGetSymbolAddress((void**)&G, g_G);
    cudaGetSymbolAddress((void**)&C, g_C);
    cudaGetSymbolAddress((void**)&S, g_S);

    static cudaStream_t s1 = nullptr;
    static cudaEvent_t  eFork = nullptr, eJoin = nullptr;
    if (!s1) {
        cudaStreamCreateWithFlags(&s1, cudaStreamNonBlocking);
        cudaEventCreateWithFlags(&eFork, cudaEventDisableTiming);
        cudaEventCreateWithFlags(&eJoin, cudaEventDisableTiming);
        cudaFuncSetAttribute(gemm_kernel,
            cudaFuncAttributeMaxDynamicSharedMemorySize, GEMM_SMEM_BYTES);
    }

    dim3 ggrid(DIM/128, ROWS/128);   // (4, 128)

    // fork: s1 <- s0
    cudaEventRecord(eFork, 0);
    cudaStreamWaitEvent(s1, eFork, 0);

    // s1: gates GEMM (depends only on q)
    gemm_kernel<<<ggrid, 256, GEMM_SMEM_BYTES, s1>>>(q, gw, gb, G, 1);
    cudaEventRecord(eJoin, s1);

    // s0: scans -> C GEMM
    scan_local <<<BATCH*NCHUNK*DIM/256, 256>>>(k, v, decay, 0);
    scan_prefix<<<BATCH*DIM/256,        256>>>(decay);
    scan_local <<<BATCH*NCHUNK*DIM/256, 256>>>(k, v, decay, 1);
    gemm_kernel<<<ggrid, 256, GEMM_SMEM_BYTES>>>(R, Bm, nullptr, C, 0);

    // join: s0 waits for G
    cudaStreamWaitEvent(0, eJoin, 0);

    // chain + fp32 out projection
    chain_kernel<<<BATCH*CLSZ, 256>>>(q, A, G, C, S);
    gemm_kernel<<<ggrid, 256, GEMM_SMEM_BYTES>>>(S, ow, ob, out, 0);
}

// round 16
// speedup vs baseline: 1.0666x; 1.0666x over previous
#include <cuda_runtime.h>
#include <cstdint>
#include <math.h>
#include <mma.h>

using namespace nvcuda;

#define BATCH 4
#define SEQ   4096
#define DIM   512
#define ROWS  (BATCH*SEQ)   // 16384
#define NCHUNK 64
#define CHUNK  (SEQ/NCHUNK) // 64
#define CLSZ   8            // cluster size for chain

// ---- scratch (no cudaMalloc allowed) ----
__device__ float g_R[ROWS*DIM];
__device__ float g_G[ROWS*DIM];
__device__ float g_C[ROWS*DIM];
__device__ float g_S[ROWS*DIM];
__device__ float g_cf[BATCH*NCHUNK*DIM];
__device__ float g_cp[BATCH*NCHUNK*DIM];

// ---------------- helpers ----------------
__device__ __forceinline__ uint32_t smem_u32(const void* p) {
    return (uint32_t)__cvta_generic_to_shared(p);
}
__device__ __forceinline__ void fma2(unsigned long long& d, unsigned long long a, unsigned long long b) {
    asm("fma.rn.f32x2 %0, %1, %2, %0;" : "+l"(d) : "l"(a), "l"(b));
}
__device__ __forceinline__ unsigned long long dupf(float a) {
    unsigned long long r;
    asm("mov.b64 %0, {%1, %1};" : "=l"(r) : "f"(a));
    return r;
}
__device__ __forceinline__ void unpack2(unsigned long long v, float& lo, float& hi) {
    asm("mov.b64 {%0, %1}, %2;" : "=f"(lo), "=f"(hi) : "l"(v));
}
__device__ __forceinline__ void mbar_init(uint32_t addr, uint32_t cnt) {
    asm volatile("mbarrier.init.shared.b64 [%0], %1;" :: "r"(addr), "r"(cnt) : "memory");
}
__device__ __forceinline__ void mbar_expect_tx(uint32_t addr, uint32_t bytes) {
    asm volatile("mbarrier.arrive.expect_tx.shared.b64 _, [%0], %1;" :: "r"(addr), "r"(bytes) : "memory");
}
__device__ __forceinline__ void st_async_u32(uint32_t raddr, uint32_t val, uint32_t rmbar) {
    asm volatile("st.async.weak.shared::cluster.mbarrier::complete_tx::bytes.b32 [%0], %1, [%2];"
                 :: "r"(raddr), "r"(val), "r"(rmbar) : "memory");
}
__device__ __forceinline__ void mbar_wait(uint32_t addr, uint32_t parity) {
    uint32_t done;
    asm volatile("{\n\t.reg .pred P;\n\t"
        "mbarrier.try_wait.parity.acquire.cta.shared::cta.b64 P, [%1], %2, 0x989680;\n\t"
        "selp.b32 %0, 1, 0, P;\n\t}"
        : "=r"(done) : "r"(addr), "r"(parity) : "memory");
    while (!done) {
        asm volatile("{\n\t.reg .pred P;\n\t"
            "mbarrier.try_wait.parity.acquire.cta.shared::cta.b64 P, [%1], %2, 0x989680;\n\t"
            "selp.b32 %0, 1, 0, P;\n\t}"
            : "=r"(done) : "r"(addr), "r"(parity) : "memory");
    }
}
#define CLUSTER_SYNC() do { \
    asm volatile("barrier.cluster.arrive.aligned;" ::: "memory"); \
    asm volatile("barrier.cluster.wait.aligned;"   ::: "memory"); } while (0)

// ============================================================
// Chunked linear scan for r
// ============================================================
__global__ void scan_local(const float* __restrict__ k, const float* __restrict__ v,
                           const float* __restrict__ decay, int store)
{
    int g = blockIdx.x*blockDim.x + threadIdx.x;
    int d = g % DIM;
    int c = (g / DIM) % NCHUNK;
    int b = g / (DIM*NCHUNK);
    float dec = decay[d >> 6];
    float r = store ? g_cp[g] : 0.0f;
    size_t base = ((size_t)b*SEQ + (size_t)c*CHUNK)*DIM + d;
    #pragma unroll 4
    for (int u = 0; u < CHUNK; u++) {
        size_t off = base + (size_t)u*DIM;
        r = fmaf(dec, r, k[off]*v[off]);
        if (store) g_R[off] = r;
    }
    if (!store) g_cf[g] = r;
}

__global__ void scan_prefix(const float* __restrict__ decay)
{
    int g = blockIdx.x*blockDim.x + threadIdx.x;
    int d = g % DIM;
    int b = g / DIM;
    float dec = decay[d >> 6];
    float dp = powf(dec, (float)CHUNK);
    float p = 0.0f;
    for (int c = 0; c < NCHUNK; c++) {
        int idx = (b*NCHUNK + c)*DIM + d;
        g_cp[idx] = p;
        p = g_cf[idx] + dp*p;
    }
}

// ============================================================
// fp32 GEMM (R13 double-buffered, f32x2) — used for G and C
// ============================================================
__global__ __launch_bounds__(256)
void gemm_kernel(const float* __restrict__ X, const float* __restrict__ W,
                 const float* __restrict__ bias, float* __restrict__ Y, int act)
{
    __shared__ __align__(16) float Xs[2][16][132];
    __shared__ __align__(16) float Ws[2][16][132];
    const int K = DIM;
    int tid  = threadIdx.x;
    int m0   = blockIdx.y * 128;
    int n0   = blockIdx.x * 128;
    int rowc = (tid >> 4) << 3;
    int colc = (tid & 15) << 3;

    int lrow0 = tid >> 2,        lfc0 = (tid & 3) << 2;
    int lrow1 = (tid+256) >> 2,  lfc1 = ((tid+256) & 3) << 2;

    unsigned long long acc2[8][4];
    #pragma unroll
    for (int i = 0; i < 8; i++)
        #pragma unroll
        for (int j = 0; j < 4; j++) acc2[i][j] = 0ull;

    {
        float4 xv = *(const float4*)(X + (size_t)(m0+lrow0)*K + lfc0);
        Xs[0][lfc0+0][lrow0]=xv.x; Xs[0][lfc0+1][lrow0]=xv.y; Xs[0][lfc0+2][lrow0]=xv.z; Xs[0][lfc0+3][lrow0]=xv.w;
        float4 wv = *(const float4*)(W + (size_t)(n0+lrow0)*K + lfc0);
        Ws[0][lfc0+0][lrow0]=wv.x; Ws[0][lfc0+1][lrow0]=wv.y; Ws[0][lfc0+2][lrow0]=wv.z; Ws[0][lfc0+3][lrow0]=wv.w;
        float4 xv1 = *(const float4*)(X + (size_t)(m0+lrow1)*K + lfc1);
        Xs[0][lfc1+0][lrow1]=xv1.x; Xs[0][lfc1+1][lrow1]=xv1.y; Xs[0][lfc1+2][lrow1]=xv1.z; Xs[0][lfc1+3][lrow1]=xv1.w;
        float4 wv1 = *(const float4*)(W + (size_t)(n0+lrow1)*K + lfc1);
        Ws[0][lfc1+0][lrow1]=wv1.x; Ws[0][lfc1+1][lrow1]=wv1.y; Ws[0][lfc1+2][lrow1]=wv1.z; Ws[0][lfc1+3][lrow1]=wv1.w;
    }
    __syncthreads();

    for (int it = 0; it < K/16; it++) {
        int cur = it & 1, nxt = 1 - cur;
        if (it + 1 < K/16) {
            int kt = (it+1)*16;
            float4 xv = *(const float4*)(X + (size_t)(m0+lrow0)*K + kt + lfc0);
            Xs[nxt][lfc0+0][lrow0]=xv.x; Xs[nxt][lfc0+1][lrow0]=xv.y; Xs[nxt][lfc0+2][lrow0]=xv.z; Xs[nxt][lfc0+3][lrow0]=xv.w;
            float4 wv = *(const float4*)(W + (size_t)(n0+lrow0)*K + kt + lfc0);
            Ws[nxt][lfc0+0][lrow0]=wv.x; Ws[nxt][lfc0+1][lrow0]=wv.y; Ws[nxt][lfc0+2][lrow0]=wv.z; Ws[nxt][lfc0+3][lrow0]=wv.w;
            float4 xv1 = *(const float4*)(X + (size_t)(m0+lrow1)*K + kt + lfc1);
            Xs[nxt][lfc1+0][lrow1]=xv1.x; Xs[nxt][lfc1+1][lrow1]=xv1.y; Xs[nxt][lfc1+2][lrow1]=xv1.z; Xs[nxt][lfc1+3][lrow1]=xv1.w;
            float4 wv1 = *(const float4*)(W + (size_t)(n0+lrow1)*K + kt + lfc1);
            Ws[nxt][lfc1+0][lrow1]=wv1.x; Ws[nxt][lfc1+1][lrow1]=wv1.y; Ws[nxt][lfc1+2][lrow1]=wv1.z; Ws[nxt][lfc1+3][lrow1]=wv1.w;
        }
        #pragma unroll
        for (int kk = 0; kk < 16; kk++) {
            float ar[8];
            *(float4*)(ar  ) = *(const float4*)&Xs[cur][kk][rowc];
            *(float4*)(ar+4) = *(const float4*)&Xs[cur][kk][rowc+4];
            ulonglong2 blo = *(const ulonglong2*)&Ws[cur][kk][colc];
            ulonglong2 bhi = *(const ulonglong2*)&Ws[cur][kk][colc+4];
            #pragma unroll
            for (int i = 0; i < 8; i++) {
                unsigned long long ad = dupf(ar[i]);
                fma2(acc2[i][0], ad, blo.x);
                fma2(acc2[i][1], ad, blo.y);
                fma2(acc2[i][2], ad, bhi.x);
                fma2(acc2[i][3], ad, bhi.y);
            }
        }
        __syncthreads();
    }

    #pragma unroll
    for (int i = 0; i < 8; i++) {
        float out[8];
        #pragma unroll
        for (int jp = 0; jp < 4; jp++) unpack2(acc2[i][jp], out[2*jp], out[2*jp+1]);
        #pragma unroll
        for (int j = 0; j < 8; j++) {
            float val = out[j] + (bias ? bias[n0+colc+j] : 0.0f);
            if (act == 1) val = 1.0f/(1.0f + expf(-val));
            Y[(size_t)(m0+rowc+i)*DIM + n0+colc+j] = val;
        }
    }
}

// ============================================================
// tf32 WMMA out-projection, k=32 slices (16 stages, 32 barriers).
// Y[M,512] = X[M,512] @ W[512,512]^T + bias
// 128x128 tile, 8 warps: warp w -> rows (w>>2)*64, cols (w&3)*32.
// As[128][36]: X rows m, k-slice cols. Bs[128][36]: W rows n, k cols
// (= B col-major, ld 36). Pad 36 keeps fragment LDS conflict-free.
// ============================================================
__global__ __launch_bounds__(256)
void out_gemm_tf32(const float* __restrict__ X, const float* __restrict__ W,
                   const float* __restrict__ bias, float* __restrict__ Y)
{
    __shared__ __align__(16) float As[128][36];
    __shared__ __align__(16) float Bs[128][36];
    __shared__ __align__(16) float stage[8][16][16];

    const int K = DIM;
    int tid  = threadIdx.x;
    int w    = tid >> 5;
    int lane = tid & 31;
    int m0   = blockIdx.y * 128;
    int n0   = blockIdx.x * 128;
    int mrow = (w >> 2) * 64;
    int ncol = (w & 3) * 32;

    // loader: 2 threads per row, 16 floats (4x float4) each
    int lrow = tid >> 1;
    int lseg = (tid & 1) * 16;

    wmma::fragment<wmma::accumulator, 16, 16, 8, float> acc[4][2];
    #pragma unroll
    for (int i = 0; i < 4; i++)
        #pragma unroll
        for (int j = 0; j < 2; j++) wmma::fill_fragment(acc[i][j], 0.0f);

    for (int kt = 0; kt < K; kt += 32) {
        #pragma unroll
        for (int s = 0; s < 4; s++) {
            *(float4*)&As[lrow][lseg + 4*s] =
                *(const float4*)(X + (size_t)(m0+lrow)*K + kt + lseg + 4*s);
            *(float4*)&Bs[lrow][lseg + 4*s] =
                *(const float4*)(W + (size_t)(n0+lrow)*K + kt + lseg + 4*s);
        }
        __syncthreads();

        #pragma unroll
        for (int ks = 0; ks < 4; ks++) {
            wmma::fragment<wmma::matrix_b, 16, 16, 8, wmma::precision::tf32, wmma::col_major> fb[2];
            #pragma unroll
            for (int j = 0; j < 2; j++) {
                wmma::load_matrix_sync(fb[j], &Bs[ncol + j*16][ks*8], 36);
                #pragma unroll
                for (int e = 0; e < fb[j].num_elements; e++)
                    fb[j].x[e] = wmma::__float_to_tf32(fb[j].x[e]);
            }
            #pragma unroll
            for (int i = 0; i < 4; i++) {
                wmma::fragment<wmma::matrix_a, 16, 16, 8, wmma::precision::tf32, wmma::row_major> fa;
                wmma::load_matrix_sync(fa, &As[mrow + i*16][ks*8], 36);
                #pragma unroll
                for (int e = 0; e < fa.num_elements; e++)
                    fa.x[e] = wmma::__float_to_tf32(fa.x[e]);
                #pragma unroll
                for (int j = 0; j < 2; j++)
                    wmma::mma_sync(acc[i][j], fa, fb[j], acc[i][j]);
            }
        }
        __syncthreads();
    }

    // epilogue: stage each 16x16 fragment, add bias, store
    #pragma unroll
    for (int i = 0; i < 4; i++) {
        #pragma unroll
        for (int j = 0; j < 2; j++) {
            wmma::store_matrix_sync(&stage[w][0][0], acc[i][j], 16, wmma::mem_row_major);
            __syncwarp();
            #pragma unroll
            for (int s = 0; s < 8; s++) {
                int e   = lane + 32*s;
                int rr  = e >> 4, cc = e & 15;
                int gm  = m0 + mrow + i*16 + rr;
                int gn  = n0 + ncol + j*16 + cc;
                Y[(size_t)gm*DIM + gn] = stage[w][rr][cc] + bias[gn];
            }
            __syncwarp();
        }
    }
}

// ============================================================
// Sequential chain: the proven structure (R6/R13), unchanged.
// ============================================================
__global__ void __launch_bounds__(256, 1) __cluster_dims__(CLSZ, 1, 1)
chain_kernel(const float* __restrict__ q, const float* __restrict__ A,
             const float* __restrict__ G, const float* __restrict__ C,
             float* __restrict__ Sout)
{
    __shared__ __align__(16) float bl[2][DIM];
    __shared__ __align__(16) float part[4][64];
    __shared__ __align__(8)  unsigned long long mbar[4];  // [buf][half]

    int rank = blockIdx.x & (CLSZ-1);
    int b    = blockIdx.x / CLSZ;
    int tid  = threadIdx.x;
    int w    = tid >> 5;
    int lane = tid & 31;
    int qw   = w >> 1;
    int rh   = w & 1;
    int jl   = rh*32 + lane;
    int jg   = rank*64 + jl;
    int kbase= qw*128;
    int hw   = qw >> 1;
    int myh  = rank >> 2;

    uint32_t bl_a = smem_u32(&bl[0][0]);
    uint32_t mb_a = smem_u32(&mbar[0]);
    uint32_t dmb  = mb_a - bl_a;

    if (tid == 0) {
        mbar_init(mb_a,      1);
        mbar_init(mb_a + 8,  1);
        mbar_init(mb_a + 16, 1);
        mbar_init(mb_a + 24, 1);
    }

    uint32_t rb[CLSZ];
    #pragma unroll
    for (int r = 0; r < CLSZ; r++)
        asm("mapa.shared::cluster.u32 %0, %1, %2;" : "=r"(rb[r]) : "r"(bl_a), "r"(r));

    unsigned long long a2[64];
    #pragma unroll
    for (int u = 0; u < 32; u++) {
        ulonglong2 av = *(const ulonglong2*)(A + (size_t)jg*DIM + kbase + 4*u);
        a2[2*u] = av.x; a2[2*u+1] = av.y;
    }

    const float* qb = q    + (size_t)b*SEQ*DIM;
    const float* Gb = G    + (size_t)b*SEQ*DIM;
    const float* Cb = C    + (size_t)b*SEQ*DIM;
    float*       Sb = Sout + (size_t)b*SEQ*DIM;

    CLUSTER_SYNC();

    int je = rank*64 + tid;
    float cc = 0.f, cg = 0.f, cq = 0.f;
    if (tid == 0) {
        mbar_expect_tx(mb_a,     1024);
        mbar_expect_tx(mb_a + 8, 1024);
    }
    if (tid < 64) {
        float g0 = Gb[je], q0 = qb[je];
        uint32_t bits = __float_as_uint((1.0f - g0) * q0);
        uint32_t moff = dmb + (uint32_t)myh*8u;
        #pragma unroll
        for (int r = 0; r < CLSZ; r++)
            st_async_u32(rb[r] + (uint32_t)je*4u, bits, rb[r] + moff);
        cc = Cb[je]; cg = Gb[DIM + je]; cq = qb[DIM + je];
    }

    for (int t = 0; t < SEQ; t++) {
        int p = t & 1;
        uint32_t ph = (t >> 1) & 1;

        float nc = 0.f, ng = 0.f, nq = 0.f;
        if (tid < 64) {
            if (t+1 < SEQ) nc = Cb[(size_t)(t+1)*DIM + je];
            if (t+2 < SEQ) { ng = Gb[(size_t)(t+2)*DIM + je]; nq = qb[(size_t)(t+2)*DIM + je]; }
        }
        if (tid == 0 && t+1 < SEQ) {
            mbar_expect_tx(mb_a + (uint32_t)(1-p)*16u,      1024);
            mbar_expect_tx(mb_a + (uint32_t)(1-p)*16u + 8u, 1024);
        }

        mbar_wait(mb_a + (uint32_t)p*16u + (uint32_t)hw*8u, ph);

        unsigned long long acc0 = 0ull, acc1 = 0ull;
        const float* blp = bl[p] + kbase;
        #pragma unroll
        for (int u = 0; u < 32; u++) {
            ulonglong2 bv = *(const ulonglong2*)(blp + 4*u);
            fma2(acc0, a2[2*u],   bv.x);
            fma2(acc1, a2[2*u+1], bv.y);
        }
        float x0, x1, y0, y1;
        unpack2(acc0, x0, x1);
        unpack2(acc1, y0, y1);
        part[qw][jl] = (x0 + x1) + (y0 + y1);

        __syncthreads();

        if (tid < 64) {
            float acc = (part[0][tid] + part[1][tid]) + (part[2][tid] + part[3][tid]);
            float s = tanhf(acc + cc);
            Sb[(size_t)t*DIM + je] = s;
            if (t+1 < SEQ) {
                uint32_t bits = __float_as_uint(fmaf(cg, s - cq, cq));
                uint32_t boff = (uint32_t)(1-p)*2048u + (uint32_t)je*4u;
                uint32_t moff = dmb + (uint32_t)(1-p)*16u + (uint32_t)myh*8u;
                #pragma unroll
                for (int r = 0; r < CLSZ; r++)
                    st_async_u32(rb[r] + boff, bits, rb[r] + moff);
            }
            cc = nc; cg = ng; cq = nq;
        }
    }
}

// ============================================================
// launch — fork-join stream overlap inside graph capture
// ============================================================
extern "C" void kernel_launch(void* const* d_in, const int* in_sizes, int n_in,
                              void* d_out, int out_size)
{
    const float* q     = (const float*)d_in[0];
    const float* k     = (const float*)d_in[1];
    const float* v     = (const float*)d_in[2];
    const float* A     = (const float*)d_in[3];
    const float* Bm    = (const float*)d_in[4];
    const float* gw    = (const float*)d_in[5];
    const float* gb    = (const float*)d_in[6];
    const float* ow    = (const float*)d_in[7];
    const float* ob    = (const float*)d_in[8];
    const float* decay = (const float*)d_in[9];
    float* out = (float*)d_out;

    float *R, *G, *C, *S;
    cudaGetSymbolAddress((void**)&R, g_R);
    cudaGetSymbolAddress((void**)&G, g_G);
    cudaGetSymbolAddress((void**)&C, g_C);
    cudaGetSymbolAddress((void**)&S, g_S);

    static cudaStream_t s1 = nullptr;
    static cudaEvent_t  eFork = nullptr, eJoin = nullptr;
    if (!s1) {
        cudaStreamCreateWithFlags(&s1, cudaStreamNonBlocking);
        cudaEventCreateWithFlags(&eFork, cudaEventDisableTiming);
        cudaEventCreateWithFlags(&eJoin, cudaEventDisableTiming);
    }

    dim3 ggrid(DIM/128, ROWS/128);   // (4, 128)

    // fork: s1 <- s0
    cudaEventRecord(eFork, 0);
    cudaStreamWaitEvent(s1, eFork, 0);

    // s1: gates GEMM (depends only on q)
    gemm_kernel<<<ggrid, 256, 0, s1>>>(q, gw, gb, G, 1);
    cudaEventRecord(eJoin, s1);

    // s0: scans -> C GEMM
    scan_local <<<BATCH*NCHUNK*DIM/256, 256>>>(k, v, decay, 0);
    scan_prefix<<<BATCH*DIM/256,        256>>>(decay);
    scan_local <<<BATCH*NCHUNK*DIM/256, 256>>>(k, v, decay, 1);
    gemm_kernel<<<ggrid, 256>>>(R, Bm, nullptr, C, 0);

    // join: s0 waits for G
    cudaStreamWaitEvent(0, eJoin, 0);

    // chain + tf32 out projection (k=32 staged)
    chain_kernel<<<BATCH*CLSZ, 256>>>(q, A, G, C, S);
    out_gemm_tf32<<<ggrid, 256>>>(S, ow, ob, out);
}